// round 8
// baseline (speedup 1.0000x reference)
#include <cuda_runtime.h>
#include <cuda_fp16.h>
#include <cuda_bf16.h>

// out[row[e]] += values[e] * x[col[e]],  row sorted ascending.
// E = 1.6M, N = 100k, D = 64.
//
// The kernel is L2-bandwidth bound (LTS cap ~6300 B/cyc): gather traffic is
// 256 B/edge = 410 MB. Halve it: pre-convert x to fp16 (12.8 MB, L2-resident),
// gather 128 B/edge, accumulate fp32. Expected global rel err ~3e-4 (fp16
// rounding), under the 1e-3 threshold.
//
// Kernel 1: edge-parallel CSR offset build (boundary detect on sorted row).
// Kernel 2: x fp32 -> fp16 table.
// Kernel 3: one warp per row, 2 edges per iteration (half-warp per edge),
//           lane owns 4 features: 8B LDG.64 gather -> 128 B/edge, 1 L1 wavefront.

#define N_NODES 100000
#define D_FEAT 64

__device__ int g_row_ptr[N_NODES + 1];
__device__ __align__(256) __half g_x_half[(size_t)N_NODES * D_FEAT];

__global__ void __launch_bounds__(256) build_row_ptr_kernel(
    const int* __restrict__ row, int n_edges, int n_nodes)
{
    int e = blockIdx.x * blockDim.x + threadIdx.x;
    if (e >= n_edges) return;
    int r = row[e];
    int prev = (e == 0) ? -1 : row[e - 1];
    for (int q = prev + 1; q <= r; ++q) g_row_ptr[q] = e;   // lower_bound fill
    if (e == n_edges - 1) {
        for (int q = r + 1; q <= n_nodes; ++q) g_row_ptr[q] = n_edges;
    }
}

__global__ void __launch_bounds__(256) convert_x_kernel(
    const float* __restrict__ x, int n4)  // n4 = total floats / 4
{
    int i = blockIdx.x * blockDim.x + threadIdx.x;
    if (i >= n4) return;
    float4 f = __ldg(&((const float4*)x)[i]);
    __half2 h0 = __floats2half2_rn(f.x, f.y);
    __half2 h1 = __floats2half2_rn(f.z, f.w);
    uint2 packed;
    packed.x = *(unsigned*)&h0;
    packed.y = *(unsigned*)&h1;
    ((uint2*)g_x_half)[i] = packed;
}

__global__ void __launch_bounds__(256) spmm_row_warp_kernel(
    const int* __restrict__ col,
    const float* __restrict__ val,
    float* __restrict__ out,
    int n_nodes)
{
    int r = (blockIdx.x * blockDim.x + threadIdx.x) >> 5;
    if (r >= n_nodes) return;
    int lane = threadIdx.x & 31;
    int half = lane >> 4;          // which edge of the pair this lane works on
    int fl   = lane & 15;          // feature lane: owns feats [4*fl, 4*fl+4)

    int s = g_row_ptr[r];
    int e = g_row_ptr[r + 1];

    const uint2* __restrict__ xh = (const uint2*)g_x_half;  // 16 uint2 per row
    float4 acc = make_float4(0.f, 0.f, 0.f, 0.f);

    #pragma unroll 4
    for (int i = s + half; i < e; i += 2) {
        int   c = __ldg(&col[i]);
        float v = __ldg(&val[i]);
        uint2 raw = __ldg(&xh[(size_t)c * (D_FEAT / 4) + fl]);  // 128B/edge gather
        __half2 h0 = *reinterpret_cast<__half2*>(&raw.x);
        __half2 h1 = *reinterpret_cast<__half2*>(&raw.y);
        float2 f0 = __half22float2(h0);
        float2 f1 = __half22float2(h1);
        acc.x = fmaf(v, f0.x, acc.x);
        acc.y = fmaf(v, f0.y, acc.y);
        acc.z = fmaf(v, f1.x, acc.z);
        acc.w = fmaf(v, f1.y, acc.w);
    }

    // combine the two half-warp partial sums (even edges + odd edges)
    acc.x += __shfl_xor_sync(0xffffffffu, acc.x, 16);
    acc.y += __shfl_xor_sync(0xffffffffu, acc.y, 16);
    acc.z += __shfl_xor_sync(0xffffffffu, acc.z, 16);
    acc.w += __shfl_xor_sync(0xffffffffu, acc.w, 16);

    if (half == 0) {
        ((float4*)out)[(size_t)r * (D_FEAT / 4) + fl] = acc;
    }
}

extern "C" void kernel_launch(void* const* d_in, const int* in_sizes, int n_in,
                              void* d_out, int out_size) {
    const int*   row = (const int*)d_in[0];
    const int*   col = (const int*)d_in[1];
    const float* val = (const float*)d_in[2];
    const float* x   = (const float*)d_in[3];
    float*       out = (float*)d_out;

    int n_edges = in_sizes[0];
    int n_x     = in_sizes[3];
    int n_nodes = n_x / D_FEAT;

    {
        int threads = 256;
        int blocks = (n_edges + threads - 1) / threads;
        build_row_ptr_kernel<<<blocks, threads>>>(row, n_edges, n_nodes);
    }
    {
        int n4 = n_x / 4;
        int threads = 256;
        int blocks = (n4 + threads - 1) / threads;
        convert_x_kernel<<<blocks, threads>>>(x, n4);
    }
    {
        int threads = 256;  // 8 warps/block, 1 row per warp
        long warps = n_nodes;
        int blocks = (int)((warps * 32 + threads - 1) / threads);
        spmm_row_warp_kernel<<<blocks, threads>>>(col, val, out, n_nodes);
    }
}

// round 9
// speedup vs baseline: 1.1543x; 1.1543x over previous
#include <cuda_runtime.h>
#include <cuda_fp16.h>
#include <cuda_bf16.h>

// out[row[e]] += values[e] * x[col[e]],  row sorted ascending.
// E = 1.6M, N = 100k, D = 64.
//
// fp16 gather table halves L2 gather traffic (410 -> 205 MB); accumulate fp32.
// Kernel 1 (fused prep): blocks [0, convBlocks) convert x -> fp16,
//                        blocks [convBlocks, ...) build CSR offsets from sorted row.
//                        Independent jobs overlap in one launch.
// Kernel 2: one warp per row, QUARTER-warp (8 lanes) per edge, 4 edges per
//           warp-iteration. Lane owns 8 fp16 feats (uint4 = 16B, LDG.128).
//           unroll 2 -> 8 gathers in flight/warp. shfl_xor reduce at end.

#define N_NODES 100000
#define D_FEAT 64

__device__ int g_row_ptr[N_NODES + 1];
__device__ __align__(256) __half g_x_half[(size_t)N_NODES * D_FEAT];

__global__ void __launch_bounds__(256) fused_prep_kernel(
    const float* __restrict__ x, int n4,          // convert job: n4 = floats/4
    const int* __restrict__ row, int n_edges,     // build job
    int n_nodes, int conv_blocks)
{
    if ((int)blockIdx.x < conv_blocks) {
        int i = blockIdx.x * blockDim.x + threadIdx.x;
        if (i >= n4) return;
        float4 f = __ldg(&((const float4*)x)[i]);
        __half2 h0 = __floats2half2_rn(f.x, f.y);
        __half2 h1 = __floats2half2_rn(f.z, f.w);
        uint2 packed;
        packed.x = *(unsigned*)&h0;
        packed.y = *(unsigned*)&h1;
        ((uint2*)g_x_half)[i] = packed;
    } else {
        int e = (blockIdx.x - conv_blocks) * blockDim.x + threadIdx.x;
        if (e >= n_edges) return;
        int r = row[e];
        int prev = (e == 0) ? -1 : row[e - 1];
        for (int q = prev + 1; q <= r; ++q) g_row_ptr[q] = e;   // lower_bound fill
        if (e == n_edges - 1) {
            for (int q = r + 1; q <= n_nodes; ++q) g_row_ptr[q] = n_edges;
        }
    }
}

__global__ void __launch_bounds__(256) spmm_row_warp_kernel(
    const int* __restrict__ col,
    const float* __restrict__ val,
    float* __restrict__ out,
    int n_nodes)
{
    int r = (blockIdx.x * blockDim.x + threadIdx.x) >> 5;
    if (r >= n_nodes) return;
    int lane = threadIdx.x & 31;
    int grp  = lane >> 3;          // which of 4 edges this lane works on
    int fl   = lane & 7;           // owns fp16 feats [8*fl, 8*fl+8)

    int s = g_row_ptr[r];
    int e = g_row_ptr[r + 1];

    const uint4* __restrict__ xq = (const uint4*)g_x_half;  // 8 uint4 per row
    float acc[8];
    #pragma unroll
    for (int k = 0; k < 8; ++k) acc[k] = 0.f;

    #pragma unroll 2
    for (int i = s + grp; i < e; i += 4) {
        int   c = __ldg(&col[i]);
        float v = __ldg(&val[i]);
        uint4 raw = __ldg(&xq[(size_t)c * (D_FEAT / 8) + fl]);  // 128B/edge, LDG.128
        const __half2* hp = reinterpret_cast<const __half2*>(&raw);
        #pragma unroll
        for (int k = 0; k < 4; ++k) {
            float2 f = __half22float2(hp[k]);
            acc[2 * k]     = fmaf(v, f.x, acc[2 * k]);
            acc[2 * k + 1] = fmaf(v, f.y, acc[2 * k + 1]);
        }
    }

    // reduce the 4 quarter-warp partials (lanes fl, fl+8, fl+16, fl+24)
    #pragma unroll
    for (int k = 0; k < 8; ++k) {
        acc[k] += __shfl_xor_sync(0xffffffffu, acc[k], 8);
        acc[k] += __shfl_xor_sync(0xffffffffu, acc[k], 16);
    }

    if (grp == 0) {
        float4* out4 = (float4*)out;
        size_t base = (size_t)r * (D_FEAT / 4) + fl * 2;
        out4[base]     = make_float4(acc[0], acc[1], acc[2], acc[3]);
        out4[base + 1] = make_float4(acc[4], acc[5], acc[6], acc[7]);
    }
}

extern "C" void kernel_launch(void* const* d_in, const int* in_sizes, int n_in,
                              void* d_out, int out_size) {
    const int*   row = (const int*)d_in[0];
    const int*   col = (const int*)d_in[1];
    const float* val = (const float*)d_in[2];
    const float* x   = (const float*)d_in[3];
    float*       out = (float*)d_out;

    int n_edges = in_sizes[0];
    int n_x     = in_sizes[3];
    int n_nodes = n_x / D_FEAT;

    {
        int threads = 256;
        int n4 = n_x / 4;
        int conv_blocks  = (n4 + threads - 1) / threads;
        int build_blocks = (n_edges + threads - 1) / threads;
        fused_prep_kernel<<<conv_blocks + build_blocks, threads>>>(
            x, n4, row, n_edges, n_nodes, conv_blocks);
    }
    {
        int threads = 256;  // 8 warps/block, 1 row per warp
        long warps = n_nodes;
        int blocks = (int)((warps * 32 + threads - 1) / threads);
        spmm_row_warp_kernel<<<blocks, threads>>>(col, val, out, n_nodes);
    }
}